// round 6
// baseline (speedup 1.0000x reference)
#include <cuda_runtime.h>

#define BSZ 4096
#define TSZ 4096
#define HBSZ 2048
#define NTOT ((long)BSZ * TSZ)

#define FIN_BLOCKS 2048
#define FIN_THREADS 256

// raw (unmasked) decoder outputs, [B][T], 16B-aligned for vector stores
__device__ __align__(16) float g_o[NTOT];
// per-block loss partial sums from finalize kernel
__device__ double g_bsum[FIN_BLOCKS];

typedef unsigned long long u64;

__device__ __forceinline__ float tanhx(float x) {
    float y; asm("tanh.approx.f32 %0, %1;" : "=f"(y) : "f"(x)); return y;
}
__device__ __forceinline__ u64 pk2(float lo, float hi) {
    u64 r; asm("mov.b64 %0, {%1, %2};" : "=l"(r) : "f"(lo), "f"(hi)); return r;
}
__device__ __forceinline__ void up2(u64 v, float& lo, float& hi) {
    asm("mov.b64 {%0, %1}, %2;" : "=f"(lo), "=f"(hi) : "l"(v));
}
// packed (a*b+c) on both f32 halves
__device__ __forceinline__ u64 f2fma(u64 a, u64 b, u64 c) {
    u64 d; asm("fma.rn.f32x2 %0, %1, %2, %3;" : "=l"(d) : "l"(a), "l"(b), "l"(c)); return d;
}

// Two independent batch chains per thread, f32x2-packed ACROSS chains.
__global__ void __launch_bounds__(32, 1) gru_kernel(
    const float* __restrict__ x, const int* __restrict__ lens,
    const float* __restrict__ eWih, const float* __restrict__ eWhh,
    const float* __restrict__ ebih, const float* __restrict__ ebhh,
    const float* __restrict__ dWih, const float* __restrict__ dWhh,
    const float* __restrict__ dbih, const float* __restrict__ dbhh,
    const float* __restrict__ linW, const float* __restrict__ linb)
{
    const int tid  = blockIdx.x * 32 + threadIdx.x;    // 0..2047
    const int bA   = tid;
    const int bB   = tid + HBSZ;
    const int lenA = lens[bA];
    const int lenB = lens[bB];
    const float* __restrict__ xrowA = x + (long)bA * TSZ;
    const float* __restrict__ xrowB = x + (long)bB * TSZ;

    const u64 HALF2 = pk2(0.5f, 0.5f);
    const u64 NEG2  = pk2(-1.0f, -1.0f);

    u64 H0 = 0ull, H1 = 0ull, H2 = 0ull;   // (h_j^A, h_j^B)

    // ================= encoder =================
    {
        // broadcast weight packs (w,w): rz gates g=0..5 pre-halved
        u64 WI[6], BS[6], W0[6], W1[6], W2[6];
#pragma unroll
        for (int g = 0; g < 6; g++) {
            float wi = 0.5f * eWih[g];
            float bs = 0.5f * (ebih[g] + ebhh[g]);
            float w0 = 0.5f * eWhh[g * 3 + 0];
            float w1 = 0.5f * eWhh[g * 3 + 1];
            float w2 = 0.5f * eWhh[g * 3 + 2];
            WI[g] = pk2(wi, wi); BS[g] = pk2(bs, bs);
            W0[g] = pk2(w0, w0); W1[g] = pk2(w1, w1); W2[g] = pk2(w2, w2);
        }
        u64 WIN[3], BIN[3], BHN[3], WN0[3], WN1[3], WN2[3];
#pragma unroll
        for (int k = 0; k < 3; k++) {
            float a;
            a = eWih[6 + k];           WIN[k] = pk2(a, a);
            a = ebih[6 + k];           BIN[k] = pk2(a, a);
            a = ebhh[6 + k];           BHN[k] = pk2(a, a);
            a = eWhh[(6 + k) * 3 + 0]; WN0[k] = pk2(a, a);
            a = eWhh[(6 + k) * 3 + 1]; WN1[k] = pk2(a, a);
            a = eWhh[(6 + k) * 3 + 2]; WN2[k] = pk2(a, a);
        }

        auto enc_step = [&](float xa, float xb, int t) {
            u64 XP = pk2(xa, xb);
            u64 A[6];
#pragma unroll
            for (int g = 0; g < 6; g++)
                A[g] = f2fma(H2, W2[g], f2fma(H1, W1[g], f2fma(H0, W0[g], f2fma(XP, WI[g], BS[g]))));
            float ta[6], tb[6];
#pragma unroll
            for (int g = 0; g < 6; g++) {
                float aa, ab; up2(A[g], aa, ab);
                ta[g] = tanhx(aa); tb[g] = tanhx(ab);
            }
            u64 R[3], Z[3];
#pragma unroll
            for (int k = 0; k < 3; k++) {
                R[k] = f2fma(pk2(ta[k],     tb[k]),     HALF2, HALF2);
                Z[k] = f2fma(pk2(ta[3 + k], tb[3 + k]), HALF2, HALF2);
            }
            u64 N[3];
#pragma unroll
            for (int k = 0; k < 3; k++) {
                u64 HN = f2fma(H2, WN2[k], f2fma(H1, WN1[k], f2fma(H0, WN0[k], BHN[k])));
                u64 I  = f2fma(XP, WIN[k], BIN[k]);
                u64 NA = f2fma(R[k], HN, I);
                float na, nb; up2(NA, na, nb);
                N[k] = pk2(tanhx(na), tanhx(nb));
            }
            // keep mask per chain (packed)
            float kA = (t < lenA) ? 1.f : 0.f;
            float kB = (t < lenB) ? 1.f : 0.f;
            u64 KM = pk2(kA, kB);
            {
                u64 HMN, HNEW, DH;
                HMN = f2fma(N[0], NEG2, H0); HNEW = f2fma(Z[0], HMN, N[0]);
                DH  = f2fma(H0, NEG2, HNEW); H0   = f2fma(KM, DH, H0);
                HMN = f2fma(N[1], NEG2, H1); HNEW = f2fma(Z[1], HMN, N[1]);
                DH  = f2fma(H1, NEG2, HNEW); H1   = f2fma(KM, DH, H1);
                HMN = f2fma(N[2], NEG2, H2); HNEW = f2fma(Z[2], HMN, N[2]);
                DH  = f2fma(H2, NEG2, HNEW); H2   = f2fma(KM, DH, H2);
            }
        };

        const int lmax  = lenA > lenB ? lenA : lenB;
        const int wmax  = __reduce_max_sync(0xFFFFFFFFu, lmax);
        const int wmax4 = (wmax + 3) & ~3;
        for (int t = 0; t < wmax4; t += 4) {
            const float4 xqA = *(const float4*)(xrowA + t);
            const float4 xqB = *(const float4*)(xrowB + t);
            enc_step(xqA.x, xqB.x, t + 0);
            enc_step(xqA.y, xqB.y, t + 1);
            enc_step(xqA.z, xqB.z, t + 2);
            enc_step(xqA.w, xqB.w, t + 3);
        }
    }

    // features = sigmoid(h): packed halve -> scalar tanh -> packed affine
    {
        u64 ZERO = 0ull;
        u64 S0 = f2fma(H0, HALF2, ZERO);
        u64 S1 = f2fma(H1, HALF2, ZERO);
        u64 S2 = f2fma(H2, HALF2, ZERO);
        float a, bb;
        up2(S0, a, bb); H0 = f2fma(pk2(tanhx(a), tanhx(bb)), HALF2, HALF2);
        up2(S1, a, bb); H1 = f2fma(pk2(tanhx(a), tanhx(bb)), HALF2, HALF2);
        up2(S2, a, bb); H2 = f2fma(pk2(tanhx(a), tanhx(bb)), HALF2, HALF2);
    }

    // ================= decoder =================
    {
        u64 WI[6], BS[6], W0[6], W1[6], W2[6];
#pragma unroll
        for (int g = 0; g < 6; g++) {
            float wi = 0.5f * dWih[g];
            float bs = 0.5f * (dbih[g] + dbhh[g]);
            float w0 = 0.5f * dWhh[g * 3 + 0];
            float w1 = 0.5f * dWhh[g * 3 + 1];
            float w2 = 0.5f * dWhh[g * 3 + 2];
            WI[g] = pk2(wi, wi); BS[g] = pk2(bs, bs);
            W0[g] = pk2(w0, w0); W1[g] = pk2(w1, w1); W2[g] = pk2(w2, w2);
        }
        u64 WIN[3], BIN[3], BHN[3], WN0[3], WN1[3], WN2[3];
#pragma unroll
        for (int k = 0; k < 3; k++) {
            float a;
            a = dWih[6 + k];           WIN[k] = pk2(a, a);
            a = dbih[6 + k];           BIN[k] = pk2(a, a);
            a = dbhh[6 + k];           BHN[k] = pk2(a, a);
            a = dWhh[(6 + k) * 3 + 0]; WN0[k] = pk2(a, a);
            a = dWhh[(6 + k) * 3 + 1]; WN1[k] = pk2(a, a);
            a = dWhh[(6 + k) * 3 + 2]; WN2[k] = pk2(a, a);
        }
        const u64 LW0 = pk2(linW[0], linW[0]);
        const u64 LW1 = pk2(linW[1], linW[1]);
        const u64 LW2 = pk2(linW[2], linW[2]);
        const u64 LB  = pk2(linb[0], linb[0]);

        u64 INP = 0ull;
        float* __restrict__ growA = g_o + (long)bA * TSZ;
        float* __restrict__ growB = g_o + (long)bB * TSZ;

        auto dec_step = [&](float& oA, float& oB) {
            u64 A[6];
#pragma unroll
            for (int g = 0; g < 6; g++)
                A[g] = f2fma(H2, W2[g], f2fma(H1, W1[g], f2fma(H0, W0[g], f2fma(INP, WI[g], BS[g]))));
            float ta[6], tb[6];
#pragma unroll
            for (int g = 0; g < 6; g++) {
                float aa, ab; up2(A[g], aa, ab);
                ta[g] = tanhx(aa); tb[g] = tanhx(ab);
            }
            u64 R[3], Z[3];
#pragma unroll
            for (int k = 0; k < 3; k++) {
                R[k] = f2fma(pk2(ta[k],     tb[k]),     HALF2, HALF2);
                Z[k] = f2fma(pk2(ta[3 + k], tb[3 + k]), HALF2, HALF2);
            }
            u64 N[3];
#pragma unroll
            for (int k = 0; k < 3; k++) {
                u64 HN = f2fma(H2, WN2[k], f2fma(H1, WN1[k], f2fma(H0, WN0[k], BHN[k])));
                u64 I  = f2fma(INP, WIN[k], BIN[k]);
                u64 NA = f2fma(R[k], HN, I);
                float na, nb; up2(NA, na, nb);
                N[k] = pk2(tanhx(na), tanhx(nb));
            }
            {
                u64 HMN;
                HMN = f2fma(N[0], NEG2, H0); H0 = f2fma(Z[0], HMN, N[0]);
                HMN = f2fma(N[1], NEG2, H1); H1 = f2fma(Z[1], HMN, N[1]);
                HMN = f2fma(N[2], NEG2, H2); H2 = f2fma(Z[2], HMN, N[2]);
            }
            u64 OUT = f2fma(H2, LW2, f2fma(H1, LW1, f2fma(H0, LW0, LB)));
            INP = OUT;
            up2(OUT, oA, oB);
        };

        for (int t = 0; t < TSZ; t += 4) {
            float a0, b0, a1, b1, a2, b2, a3, b3;
            dec_step(a0, b0);
            dec_step(a1, b1);
            dec_step(a2, b2);
            dec_step(a3, b3);
            *(float4*)(growA + t) = make_float4(a0, a1, a2, a3);
            *(float4*)(growB + t) = make_float4(b0, b1, b2, b3);
        }
    }
}

// Fused elementwise pass: xpad, masked output copy, loss partials.
__global__ void finalize_kernel(const float* __restrict__ x,
                                const int* __restrict__ lens,
                                float* __restrict__ xpad,
                                float* __restrict__ outmasked)
{
    __shared__ double s[FIN_THREADS];
    const int tid = threadIdx.x;
    float acc = 0.f;
    for (long idx = (long)blockIdx.x * FIN_THREADS + tid; idx < NTOT;
         idx += (long)FIN_BLOCKS * FIN_THREADS) {
        int b = (int)(idx >> 12);
        int t = (int)(idx & (TSZ - 1));
        bool v = t < lens[b];
        float xv = x[idx];
        float ov = g_o[idx];
        float xm = v ? xv : 0.f;
        float om = v ? ov : 0.f;
        xpad[idx]      = xm;
        outmasked[idx] = om;
        float d = xm - om;
        acc = fmaf(d, d, acc);
    }
    s[tid] = (double)acc;
    __syncthreads();
    for (int off = FIN_THREADS / 2; off > 0; off >>= 1) {
        if (tid < off) s[tid] += s[tid + off];
        __syncthreads();
    }
    if (tid == 0) g_bsum[blockIdx.x] = s[0];
}

// Deterministic fixed-order reduction of block partials -> scalar loss
__global__ void loss_kernel(float* __restrict__ out_loss)
{
    __shared__ double s[1024];
    int tid = threadIdx.x;
    double a = 0.0;
    for (int i = tid; i < FIN_BLOCKS; i += 1024) a += g_bsum[i];
    s[tid] = a;
    __syncthreads();
    for (int off = 512; off > 0; off >>= 1) {
        if (tid < off) s[tid] += s[tid + off];
        __syncthreads();
    }
    if (tid == 0) out_loss[0] = (float)(s[0] / ((double)BSZ * (double)TSZ));
}

extern "C" void kernel_launch(void* const* d_in, const int* in_sizes, int n_in,
                              void* d_out, int out_size)
{
    const float* x    = (const float*)d_in[0];
    const int*   lens = (const int*)  d_in[1];
    const float* eWih = (const float*)d_in[2];
    const float* eWhh = (const float*)d_in[3];
    const float* ebih = (const float*)d_in[4];
    const float* ebhh = (const float*)d_in[5];
    const float* dWih = (const float*)d_in[6];
    const float* dWhh = (const float*)d_in[7];
    const float* dbih = (const float*)d_in[8];
    const float* dbhh = (const float*)d_in[9];
    const float* linW = (const float*)d_in[10];
    const float* linb = (const float*)d_in[11];

    float* out    = (float*)d_out;
    float* loss   = out;                       // [1]
    float* xpad   = out + 1;                   // [B*T]
    float* output = out + 1 + NTOT;            // [B*T]

    gru_kernel<<<HBSZ / 32, 32>>>(x, lens, eWih, eWhh, ebih, ebhh,
                                  dWih, dWhh, dbih, dbhh, linW, linb);
    finalize_kernel<<<FIN_BLOCKS, FIN_THREADS>>>(x, lens, xpad, output);
    loss_kernel<<<1, 1024>>>(loss);
}

// round 7
// speedup vs baseline: 1.7802x; 1.7802x over previous
#include <cuda_runtime.h>

#define BSZ 4096
#define TSZ 4096
#define NTOT ((long)BSZ * TSZ)

#define GRU_THREADS 256      // 8 warps/block -> 2 warps per SMSP
#define GRU_BLOCKS  (BSZ / GRU_THREADS)   // 16

#define FIN_BLOCKS 2048
#define FIN_THREADS 256

// raw (unmasked) decoder outputs, [B][T], 16B-aligned for vector stores
__device__ __align__(16) float g_o[NTOT];
// per-block loss partial sums from finalize kernel
__device__ double g_bsum[FIN_BLOCKS];

typedef unsigned long long u64;

__device__ __forceinline__ float tanhx(float x) {
    float y; asm("tanh.approx.f32 %0, %1;" : "=f"(y) : "f"(x)); return y;
}
__device__ __forceinline__ u64 pk2(float lo, float hi) {
    u64 r; asm("mov.b64 %0, {%1, %2};" : "=l"(r) : "f"(lo), "f"(hi)); return r;
}
__device__ __forceinline__ void up2(u64 v, float& lo, float& hi) {
    asm("mov.b64 {%0, %1}, %2;" : "=f"(lo), "=f"(hi) : "l"(v));
}
// packed (a*b+c) on both f32 halves — single FFMA2-class op on the fma pipe
__device__ __forceinline__ u64 f2fma(u64 a, u64 b, u64 c) {
    u64 d; asm("fma.rn.f32x2 %0, %1, %2, %3;" : "=l"(d) : "l"(a), "l"(b), "l"(c)); return d;
}

// One chain per thread; gate math packed pairwise into f32x2 (R5 body).
// Launched 16 x 256 so each SMSP hosts 2 warps that fill each other's stalls.
__global__ void __launch_bounds__(GRU_THREADS, 1) gru_kernel(
    const float* __restrict__ x, const int* __restrict__ lens,
    const float* __restrict__ eWih, const float* __restrict__ eWhh,
    const float* __restrict__ ebih, const float* __restrict__ ebhh,
    const float* __restrict__ dWih, const float* __restrict__ dWhh,
    const float* __restrict__ dbih, const float* __restrict__ dbhh,
    const float* __restrict__ linW, const float* __restrict__ linb)
{
    const int b   = blockIdx.x * GRU_THREADS + threadIdx.x;
    const int len = lens[b];
    const float* __restrict__ xrow = x + (long)b * TSZ;

    const u64 HALF2 = pk2(0.5f, 0.5f);
    const u64 NEG2  = pk2(-1.0f, -1.0f);

    float h0 = 0.f, h1 = 0.f, h2 = 0.f;
    float c0 = 0.f, c1 = 0.f, c2 = 0.f;   // captured h at t == len-1

    // ================= encoder =================
    {
        // r/z gates paired (r_k, z_k), pre-halved for sigmoid-via-tanh
        u64 WIrz[3], BSrz[3], WH0rz[3], WH1rz[3], WH2rz[3];
#pragma unroll
        for (int k = 0; k < 3; k++) {
            WIrz[k]  = pk2(0.5f * eWih[k],                 0.5f * eWih[3 + k]);
            BSrz[k]  = pk2(0.5f * (ebih[k] + ebhh[k]),     0.5f * (ebih[3 + k] + ebhh[3 + k]));
            WH0rz[k] = pk2(0.5f * eWhh[k * 3 + 0],         0.5f * eWhh[(3 + k) * 3 + 0]);
            WH1rz[k] = pk2(0.5f * eWhh[k * 3 + 1],         0.5f * eWhh[(3 + k) * 3 + 1]);
            WH2rz[k] = pk2(0.5f * eWhh[k * 3 + 2],         0.5f * eWhh[(3 + k) * 3 + 2]);
        }
        // n gates: (n0,n1) packed + n2 scalar
        const u64 WIN01 = pk2(eWih[6], eWih[7]);
        const u64 BIN01 = pk2(ebih[6], ebih[7]);
        const u64 BHN01 = pk2(ebhh[6], ebhh[7]);
        const u64 WHN0  = pk2(eWhh[18], eWhh[21]);
        const u64 WHN1  = pk2(eWhh[19], eWhh[22]);
        const u64 WHN2  = pk2(eWhh[20], eWhh[23]);
        const float win2 = eWih[8], bin2 = ebih[8], bhn2 = ebhh[8];
        const float whn20 = eWhh[24], whn21 = eWhh[25], whn22 = eWhh[26];
        const int len_m1 = len - 1;

        auto enc_step = [&](float xv, int t) {
            u64 xp  = pk2(xv, xv);
            u64 hh0 = pk2(h0, h0), hh1 = pk2(h1, h1), hh2 = pk2(h2, h2);
            u64 arz0 = f2fma(hh2, WH2rz[0], f2fma(hh1, WH1rz[0], f2fma(hh0, WH0rz[0], f2fma(xp, WIrz[0], BSrz[0]))));
            u64 arz1 = f2fma(hh2, WH2rz[1], f2fma(hh1, WH1rz[1], f2fma(hh0, WH0rz[1], f2fma(xp, WIrz[1], BSrz[1]))));
            u64 arz2 = f2fma(hh2, WH2rz[2], f2fma(hh1, WH1rz[2], f2fma(hh0, WH0rz[2], f2fma(xp, WIrz[2], BSrz[2]))));
            float ar0, az0, ar1, az1, ar2, az2;
            up2(arz0, ar0, az0); up2(arz1, ar1, az1); up2(arz2, ar2, az2);
            float tr0 = tanhx(ar0), tr1 = tanhx(ar1), tr2 = tanhx(ar2);
            float tz0 = tanhx(az0), tz1 = tanhx(az1), tz2 = tanhx(az2);
            u64 r01 = f2fma(pk2(tr0, tr1), HALF2, HALF2);
            u64 z01 = f2fma(pk2(tz0, tz1), HALF2, HALF2);
            float r2 = fmaf(tr2, 0.5f, 0.5f), z2 = fmaf(tz2, 0.5f, 0.5f);

            u64 hn01 = f2fma(hh2, WHN2, f2fma(hh1, WHN1, f2fma(hh0, WHN0, BHN01)));
            float hn2 = fmaf(h2, whn22, fmaf(h1, whn21, fmaf(h0, whn20, bhn2)));
            u64 i01 = f2fma(xp, WIN01, BIN01);
            float i2 = fmaf(xv, win2, bin2);

            u64 na01 = f2fma(r01, hn01, i01);
            float na0, na1; up2(na01, na0, na1);
            float n0 = tanhx(na0), n1 = tanhx(na1);
            float n2 = tanhx(fmaf(r2, hn2, i2));

            u64 n01p = pk2(n0, n1);
            u64 h01p = pk2(h0, h1);
            u64 hmn  = f2fma(n01p, NEG2, h01p);     // h - n
            u64 h01n = f2fma(z01, hmn, n01p);
            up2(h01n, h0, h1);
            h2 = fmaf(z2, h2 - n2, n2);

            // capture final hidden state off the critical chain
            if (t == len_m1) { c0 = h0; c1 = h1; c2 = h2; }
        };

        const int wmax  = __reduce_max_sync(0xFFFFFFFFu, len);
        const int wmax4 = (wmax + 3) & ~3;
        for (int t = 0; t < wmax4; t += 4) {
            const float4 xq = *(const float4*)(xrow + t);
            enc_step(xq.x, t + 0);
            enc_step(xq.y, t + 1);
            enc_step(xq.z, t + 2);
            enc_step(xq.w, t + 3);
        }
    }

    // features = sigmoid(captured h)
    h0 = fmaf(tanhx(0.5f * c0), 0.5f, 0.5f);
    h1 = fmaf(tanhx(0.5f * c1), 0.5f, 0.5f);
    h2 = fmaf(tanhx(0.5f * c2), 0.5f, 0.5f);

    // ================= decoder =================
    {
        u64 WIrz[3], BSrz[3], WH0rz[3], WH1rz[3], WH2rz[3];
#pragma unroll
        for (int k = 0; k < 3; k++) {
            WIrz[k]  = pk2(0.5f * dWih[k],                 0.5f * dWih[3 + k]);
            BSrz[k]  = pk2(0.5f * (dbih[k] + dbhh[k]),     0.5f * (dbih[3 + k] + dbhh[3 + k]));
            WH0rz[k] = pk2(0.5f * dWhh[k * 3 + 0],         0.5f * dWhh[(3 + k) * 3 + 0]);
            WH1rz[k] = pk2(0.5f * dWhh[k * 3 + 1],         0.5f * dWhh[(3 + k) * 3 + 1]);
            WH2rz[k] = pk2(0.5f * dWhh[k * 3 + 2],         0.5f * dWhh[(3 + k) * 3 + 2]);
        }
        const u64 WIN01 = pk2(dWih[6], dWih[7]);
        const u64 BIN01 = pk2(dbih[6], dbih[7]);
        const u64 BHN01 = pk2(dbhh[6], dbhh[7]);
        const u64 WHN0  = pk2(dWhh[18], dWhh[21]);
        const u64 WHN1  = pk2(dWhh[19], dWhh[22]);
        const u64 WHN2  = pk2(dWhh[20], dWhh[23]);
        const float win2 = dWih[8], bin2 = dbih[8], bhn2 = dbhh[8];
        const float whn20 = dWhh[24], whn21 = dWhh[25], whn22 = dWhh[26];
        const float lw0 = linW[0], lw1 = linW[1], lw2 = linW[2], lb = linb[0];

        float inp = 0.f;
        float* __restrict__ grow = g_o + (long)b * TSZ;

        auto dec_step = [&]() -> float {
            u64 xp  = pk2(inp, inp);
            u64 hh0 = pk2(h0, h0), hh1 = pk2(h1, h1), hh2 = pk2(h2, h2);
            u64 arz0 = f2fma(hh2, WH2rz[0], f2fma(hh1, WH1rz[0], f2fma(hh0, WH0rz[0], f2fma(xp, WIrz[0], BSrz[0]))));
            u64 arz1 = f2fma(hh2, WH2rz[1], f2fma(hh1, WH1rz[1], f2fma(hh0, WH0rz[1], f2fma(xp, WIrz[1], BSrz[1]))));
            u64 arz2 = f2fma(hh2, WH2rz[2], f2fma(hh1, WH1rz[2], f2fma(hh0, WH0rz[2], f2fma(xp, WIrz[2], BSrz[2]))));
            float ar0, az0, ar1, az1, ar2, az2;
            up2(arz0, ar0, az0); up2(arz1, ar1, az1); up2(arz2, ar2, az2);
            float tr0 = tanhx(ar0), tr1 = tanhx(ar1), tr2 = tanhx(ar2);
            float tz0 = tanhx(az0), tz1 = tanhx(az1), tz2 = tanhx(az2);
            u64 r01 = f2fma(pk2(tr0, tr1), HALF2, HALF2);
            u64 z01 = f2fma(pk2(tz0, tz1), HALF2, HALF2);
            float r2 = fmaf(tr2, 0.5f, 0.5f), z2 = fmaf(tz2, 0.5f, 0.5f);

            u64 hn01 = f2fma(hh2, WHN2, f2fma(hh1, WHN1, f2fma(hh0, WHN0, BHN01)));
            float hn2 = fmaf(h2, whn22, fmaf(h1, whn21, fmaf(h0, whn20, bhn2)));
            u64 i01 = f2fma(xp, WIN01, BIN01);
            float i2 = fmaf(inp, win2, bin2);

            u64 na01 = f2fma(r01, hn01, i01);
            float na0, na1; up2(na01, na0, na1);
            float n0 = tanhx(na0), n1 = tanhx(na1);
            float n2 = tanhx(fmaf(r2, hn2, i2));

            u64 n01p = pk2(n0, n1);
            u64 h01p = pk2(h0, h1);
            u64 hmn  = f2fma(n01p, NEG2, h01p);
            u64 h01n = f2fma(z01, hmn, n01p);
            up2(h01n, h0, h1);
            h2 = fmaf(z2, h2 - n2, n2);

            float outv = fmaf(h2, lw2, fmaf(h1, lw1, fmaf(h0, lw0, lb)));
            inp = outv;
            return outv;
        };

        for (int t = 0; t < TSZ; t += 4) {
            float o0 = dec_step();
            float o1 = dec_step();
            float o2 = dec_step();
            float o3 = dec_step();
            *(float4*)(grow + t) = make_float4(o0, o1, o2, o3);
        }
    }
}

// Fused elementwise pass: xpad, masked output copy, loss partials.
__global__ void finalize_kernel(const float* __restrict__ x,
                                const int* __restrict__ lens,
                                float* __restrict__ xpad,
                                float* __restrict__ outmasked)
{
    __shared__ double s[FIN_THREADS];
    const int tid = threadIdx.x;
    float acc = 0.f;
    for (long idx = (long)blockIdx.x * FIN_THREADS + tid; idx < NTOT;
         idx += (long)FIN_BLOCKS * FIN_THREADS) {
        int b = (int)(idx >> 12);
        int t = (int)(idx & (TSZ - 1));
        bool v = t < lens[b];
        float xv = x[idx];
        float ov = g_o[idx];
        float xm = v ? xv : 0.f;
        float om = v ? ov : 0.f;
        xpad[idx]      = xm;
        outmasked[idx] = om;
        float d = xm - om;
        acc = fmaf(d, d, acc);
    }
    s[tid] = (double)acc;
    __syncthreads();
    for (int off = FIN_THREADS / 2; off > 0; off >>= 1) {
        if (tid < off) s[tid] += s[tid + off];
        __syncthreads();
    }
    if (tid == 0) g_bsum[blockIdx.x] = s[0];
}

// Deterministic fixed-order reduction of block partials -> scalar loss
__global__ void loss_kernel(float* __restrict__ out_loss)
{
    __shared__ double s[1024];
    int tid = threadIdx.x;
    double a = 0.0;
    for (int i = tid; i < FIN_BLOCKS; i += 1024) a += g_bsum[i];
    s[tid] = a;
    __syncthreads();
    for (int off = 512; off > 0; off >>= 1) {
        if (tid < off) s[tid] += s[tid + off];
        __syncthreads();
    }
    if (tid == 0) out_loss[0] = (float)(s[0] / ((double)BSZ * (double)TSZ));
}

extern "C" void kernel_launch(void* const* d_in, const int* in_sizes, int n_in,
                              void* d_out, int out_size)
{
    const float* x    = (const float*)d_in[0];
    const int*   lens = (const int*)  d_in[1];
    const float* eWih = (const float*)d_in[2];
    const float* eWhh = (const float*)d_in[3];
    const float* ebih = (const float*)d_in[4];
    const float* ebhh = (const float*)d_in[5];
    const float* dWih = (const float*)d_in[6];
    const float* dWhh = (const float*)d_in[7];
    const float* dbih = (const float*)d_in[8];
    const float* dbhh = (const float*)d_in[9];
    const float* linW = (const float*)d_in[10];
    const float* linb = (const float*)d_in[11];

    float* out    = (float*)d_out;
    float* loss   = out;                       // [1]
    float* xpad   = out + 1;                   // [B*T]
    float* output = out + 1 + NTOT;            // [B*T]

    gru_kernel<<<GRU_BLOCKS, GRU_THREADS>>>(x, lens, eWih, eWhh, ebih, ebhh,
                                            dWih, dWhh, dbih, dbhh, linW, linb);
    finalize_kernel<<<FIN_BLOCKS, FIN_THREADS>>>(x, lens, xpad, output);
    loss_kernel<<<1, 1024>>>(loss);
}

// round 8
// speedup vs baseline: 2.1674x; 1.2175x over previous
#include <cuda_runtime.h>

#define BSZ 4096
#define TSZ 4096
#define NTOT ((long)BSZ * TSZ)

#define FIN_BLOCKS 2048
#define FIN_THREADS 256

// raw (unmasked) decoder outputs, [B][T], 16B-aligned for vector stores
__device__ __align__(16) float g_o[NTOT];
// per-block loss partial sums from finalize kernel
__device__ double g_bsum[FIN_BLOCKS];

__device__ __forceinline__ float tanhx(float x) {
    float y; asm("tanh.approx.f32 %0, %1;" : "=f"(y) : "f"(x)); return y;
}

// One thread per batch element, all-scalar, chain-minimized.
// 128 blocks x 32 threads (proven best spread: 1 warp per SM).
__global__ void __launch_bounds__(32, 1) gru_kernel(
    const float* __restrict__ x, const int* __restrict__ lens,
    const float* __restrict__ eWih, const float* __restrict__ eWhh,
    const float* __restrict__ ebih, const float* __restrict__ ebhh,
    const float* __restrict__ dWih, const float* __restrict__ dWhh,
    const float* __restrict__ dbih, const float* __restrict__ dbhh,
    const float* __restrict__ linW, const float* __restrict__ linb)
{
    const int b   = blockIdx.x * 32 + threadIdx.x;
    const int len = lens[b];
    const float* __restrict__ xrow = x + (long)b * TSZ;

    float h0 = 0.f, h1 = 0.f, h2 = 0.f;
    float c0 = 0.f, c1 = 0.f, c2 = 0.f;      // captured h at t == len-1

    // ================= encoder =================
    {
        // rz gates g=0..5 ([r0,r1,r2,z0,z1,z2]), args pre-halved for sigmoid-via-tanh
        float wi[6], bs[6], w0[6], w1[6], w2[6];
#pragma unroll
        for (int g = 0; g < 6; g++) {
            wi[g] = 0.5f * eWih[g];
            bs[g] = 0.5f * (ebih[g] + ebhh[g]);
            w0[g] = 0.5f * eWhh[g * 3 + 0];
            w1[g] = 0.5f * eWhh[g * 3 + 1];
            w2[g] = 0.5f * eWhh[g * 3 + 2];
        }
        float win[3], bin_[3], bhn[3], wn0[3], wn1[3], wn2[3];
#pragma unroll
        for (int k = 0; k < 3; k++) {
            win[k]  = eWih[6 + k];
            bin_[k] = ebih[6 + k];
            bhn[k]  = ebhh[6 + k];
            wn0[k]  = eWhh[(6 + k) * 3 + 0];
            wn1[k]  = eWhh[(6 + k) * 3 + 1];
            wn2[k]  = eWhh[(6 + k) * 3 + 2];
        }
        const int len_m1 = len - 1;

        auto enc_step = [&](float xv, int t) {
            // x-part: independent of h, schedulable ahead of the chain
            float gi[6];
#pragma unroll
            for (int g = 0; g < 6; g++) gi[g] = fmaf(xv, wi[g], bs[g]);
            float i0 = fmaf(xv, win[0], bin_[0]);
            float i1 = fmaf(xv, win[1], bin_[1]);
            float i2 = fmaf(xv, win[2], bin_[2]);

            // h-chain dots (3 serial fma each, independent across gates)
            float a[6];
#pragma unroll
            for (int g = 0; g < 6; g++)
                a[g] = fmaf(h2, w2[g], fmaf(h1, w1[g], fmaf(h0, w0[g], gi[g])));
            float hn0 = fmaf(h2, wn2[0], fmaf(h1, wn1[0], fmaf(h0, wn0[0], bhn[0])));
            float hn1 = fmaf(h2, wn2[1], fmaf(h1, wn1[1], fmaf(h0, wn0[1], bhn[1])));
            float hn2 = fmaf(h2, wn2[2], fmaf(h1, wn1[2], fmaf(h0, wn0[2], bhn[2])));

            float tr0 = tanhx(a[0]), tr1 = tanhx(a[1]), tr2 = tanhx(a[2]);
            float tz0 = tanhx(a[3]), tz1 = tanhx(a[4]), tz2 = tanhx(a[5]);

            float r0 = fmaf(tr0, 0.5f, 0.5f), r1 = fmaf(tr1, 0.5f, 0.5f), r2 = fmaf(tr2, 0.5f, 0.5f);
            float z0 = fmaf(tz0, 0.5f, 0.5f), z1 = fmaf(tz1, 0.5f, 0.5f), z2 = fmaf(tz2, 0.5f, 0.5f);
            // off-chain prep during tanh shadow: omz = 1-z, u = z*h
            float m0 = fmaf(tz0, -0.5f, 0.5f), m1 = fmaf(tz1, -0.5f, 0.5f), m2 = fmaf(tz2, -0.5f, 0.5f);
            float u0 = z0 * h0, u1 = z1 * h1, u2 = z2 * h2;

            float n0 = tanhx(fmaf(r0, hn0, i0));
            float n1 = tanhx(fmaf(r1, hn1, i1));
            float n2 = tanhx(fmaf(r2, hn2, i2));

            // single fma after the tanh: h = n*(1-z) + z*h
            float nh0 = fmaf(n0, m0, u0);
            float nh1 = fmaf(n1, m1, u1);
            float nh2 = fmaf(n2, m2, u2);
            bool act = t < len;
            h0 = act ? nh0 : h0;
            h1 = act ? nh1 : h1;
            h2 = act ? nh2 : h2;
            if (t == len_m1) { c0 = h0; c1 = h1; c2 = h2; }
        };

        const int wmax  = __reduce_max_sync(0xFFFFFFFFu, len);
        const int wmax4 = (wmax + 3) & ~3;
        for (int t = 0; t < wmax4; t += 4) {
            const float4 xq = *(const float4*)(xrow + t);
            enc_step(xq.x, t + 0);
            enc_step(xq.y, t + 1);
            enc_step(xq.z, t + 2);
            enc_step(xq.w, t + 3);
        }
    }

    // features = sigmoid(captured h)
    h0 = fmaf(tanhx(0.5f * c0), 0.5f, 0.5f);
    h1 = fmaf(tanhx(0.5f * c1), 0.5f, 0.5f);
    h2 = fmaf(tanhx(0.5f * c2), 0.5f, 0.5f);

    // ================= decoder =================
    {
        float wi[6], bs[6], w0[6], w1[6], w2[6];
#pragma unroll
        for (int g = 0; g < 6; g++) {
            wi[g] = 0.5f * dWih[g];
            bs[g] = 0.5f * (dbih[g] + dbhh[g]);
            w0[g] = 0.5f * dWhh[g * 3 + 0];
            w1[g] = 0.5f * dWhh[g * 3 + 1];
            w2[g] = 0.5f * dWhh[g * 3 + 2];
        }
        float win[3], bin_[3], bhn[3], wn0[3], wn1[3], wn2[3];
#pragma unroll
        for (int k = 0; k < 3; k++) {
            win[k]  = dWih[6 + k];
            bin_[k] = dbih[6 + k];
            bhn[k]  = dbhh[6 + k];
            wn0[k]  = dWhh[(6 + k) * 3 + 0];
            wn1[k]  = dWhh[(6 + k) * 3 + 1];
            wn2[k]  = dWhh[(6 + k) * 3 + 2];
        }
        const float lw0 = linW[0], lw1 = linW[1], lw2 = linW[2], lb = linb[0];

        float inp = 0.f;
        float* __restrict__ grow = g_o + (long)b * TSZ;

        auto dec_step = [&]() -> float {
            // gate dots: h-terms innermost (start as soon as h is ready),
            // inp-term outermost (inp was finalized during previous step's tail)
            float a[6];
#pragma unroll
            for (int g = 0; g < 6; g++)
                a[g] = fmaf(inp, wi[g], fmaf(h2, w2[g], fmaf(h1, w1[g], fmaf(h0, w0[g], bs[g]))));
            float hn0 = fmaf(h2, wn2[0], fmaf(h1, wn1[0], fmaf(h0, wn0[0], bhn[0])));
            float hn1 = fmaf(h2, wn2[1], fmaf(h1, wn1[1], fmaf(h0, wn0[1], bhn[1])));
            float hn2 = fmaf(h2, wn2[2], fmaf(h1, wn1[2], fmaf(h0, wn0[2], bhn[2])));
            // i_n: inp is ready at step entry -> off the h-chain
            float i0 = fmaf(inp, win[0], bin_[0]);
            float i1 = fmaf(inp, win[1], bin_[1]);
            float i2 = fmaf(inp, win[2], bin_[2]);

            float tr0 = tanhx(a[0]), tr1 = tanhx(a[1]), tr2 = tanhx(a[2]);
            float tz0 = tanhx(a[3]), tz1 = tanhx(a[4]), tz2 = tanhx(a[5]);

            float r0 = fmaf(tr0, 0.5f, 0.5f), r1 = fmaf(tr1, 0.5f, 0.5f), r2 = fmaf(tr2, 0.5f, 0.5f);
            float z0 = fmaf(tz0, 0.5f, 0.5f), z1 = fmaf(tz1, 0.5f, 0.5f), z2 = fmaf(tz2, 0.5f, 0.5f);
            float m0 = fmaf(tz0, -0.5f, 0.5f), m1 = fmaf(tz1, -0.5f, 0.5f), m2 = fmaf(tz2, -0.5f, 0.5f);
            float u0 = z0 * h0, u1 = z1 * h1, u2 = z2 * h2;

            float n0 = tanhx(fmaf(r0, hn0, i0));
            float n1 = tanhx(fmaf(r1, hn1, i1));
            float n2 = tanhx(fmaf(r2, hn2, i2));

            h0 = fmaf(n0, m0, u0);
            h1 = fmaf(n1, m1, u1);
            h2 = fmaf(n2, m2, u2);

            // output linear: off the gate chain (only consumed as next inp-outer term)
            float outv = fmaf(h2, lw2, fmaf(h1, lw1, fmaf(h0, lw0, lb)));
            inp = outv;
            return outv;
        };

        for (int t = 0; t < TSZ; t += 4) {
            float o0 = dec_step();
            float o1 = dec_step();
            float o2 = dec_step();
            float o3 = dec_step();
            *(float4*)(grow + t) = make_float4(o0, o1, o2, o3);
        }
    }
}

// Fused elementwise pass: xpad, masked output copy, loss partials.
__global__ void finalize_kernel(const float* __restrict__ x,
                                const int* __restrict__ lens,
                                float* __restrict__ xpad,
                                float* __restrict__ outmasked)
{
    __shared__ double s[FIN_THREADS];
    const int tid = threadIdx.x;
    float acc = 0.f;
    for (long idx = (long)blockIdx.x * FIN_THREADS + tid; idx < NTOT;
         idx += (long)FIN_BLOCKS * FIN_THREADS) {
        int b = (int)(idx >> 12);
        int t = (int)(idx & (TSZ - 1));
        bool v = t < lens[b];
        float xv = x[idx];
        float ov = g_o[idx];
        float xm = v ? xv : 0.f;
        float om = v ? ov : 0.f;
        xpad[idx]      = xm;
        outmasked[idx] = om;
        float d = xm - om;
        acc = fmaf(d, d, acc);
    }
    s[tid] = (double)acc;
    __syncthreads();
    for (int off = FIN_THREADS / 2; off > 0; off >>= 1) {
        if (tid < off) s[tid] += s[tid + off];
        __syncthreads();
    }
    if (tid == 0) g_bsum[blockIdx.x] = s[0];
}

// Deterministic fixed-order reduction of block partials -> scalar loss
__global__ void loss_kernel(float* __restrict__ out_loss)
{
    __shared__ double s[1024];
    int tid = threadIdx.x;
    double a = 0.0;
    for (int i = tid; i < FIN_BLOCKS; i += 1024) a += g_bsum[i];
    s[tid] = a;
    __syncthreads();
    for (int off = 512; off > 0; off >>= 1) {
        if (tid < off) s[tid] += s[tid + off];
        __syncthreads();
    }
    if (tid == 0) out_loss[0] = (float)(s[0] / ((double)BSZ * (double)TSZ));
}

extern "C" void kernel_launch(void* const* d_in, const int* in_sizes, int n_in,
                              void* d_out, int out_size)
{
    const float* x    = (const float*)d_in[0];
    const int*   lens = (const int*)  d_in[1];
    const float* eWih = (const float*)d_in[2];
    const float* eWhh = (const float*)d_in[3];
    const float* ebih = (const float*)d_in[4];
    const float* ebhh = (const float*)d_in[5];
    const float* dWih = (const float*)d_in[6];
    const float* dWhh = (const float*)d_in[7];
    const float* dbih = (const float*)d_in[8];
    const float* dbhh = (const float*)d_in[9];
    const float* linW = (const float*)d_in[10];
    const float* linb = (const float*)d_in[11];

    float* out    = (float*)d_out;
    float* loss   = out;                       // [1]
    float* xpad   = out + 1;                   // [B*T]
    float* output = out + 1 + NTOT;            // [B*T]

    gru_kernel<<<BSZ / 32, 32>>>(x, lens, eWih, eWhh, ebih, ebhh,
                                 dWih, dWhh, dbih, dbhh, linW, linb);
    finalize_kernel<<<FIN_BLOCKS, FIN_THREADS>>>(x, lens, xpad, output);
    loss_kernel<<<1, 1024>>>(loss);
}